// round 5
// baseline (speedup 1.0000x reference)
#include <cuda_runtime.h>
#include <math_constants.h>

#define BATCH 64
#define N 1024
#define RBLKS 32            // row-blocks per batch (32 rows each)

// Scratch: row offsets R[b][i], col offsets C[b][j], per-CTA column partials
__device__ float g_R[BATCH * N];
__device__ float g_C[BATCH * N];
__device__ float g_part[BATCH * RBLKS * N];   // 8 MB

// ---------------------------------------------------------------------------
// Fused pass (one read of s does a row iteration AND a column iteration):
//   per row i:  sum_i = sum_j exp(s[i][j] - C[j]);  R[i] = log(sum_i)
//   column partials: part[j] += sum_i exp(s[i][j] - C[j] - R[i])
// finalize_col forms C_new[j] = log(sum_blocks part) + C_old[j].
// Warp-per-row. exp values are spilled to PER-WARP smem (each lane reads back
// only what it wrote -> no barriers, no conflicts) to keep regs ~48 and
// occupancy at 5 CTAs/SM for enough loads in flight.
// grid = (RBLKS, BATCH), block = 256 (8 warps, 4 rows each).
// No max-subtraction needed: exp args bounded (logsumexp >= max).
// ---------------------------------------------------------------------------
template <bool USE_C>
__global__ void __launch_bounds__(256) fused_pass(const float* __restrict__ s) {
    __shared__ float c_s[N];
    __shared__ float stage[8][N];      // 32 KB: per-warp private e-spill
    const int b = blockIdx.y;
    if (USE_C) {
        #pragma unroll
        for (int t = threadIdx.x; t < N; t += 256) c_s[t] = g_C[b * N + t];
        __syncthreads();
    }

    const int warp = threadIdx.x >> 5;
    const int lane = threadIdx.x & 31;
    const int tid  = threadIdx.x;
    float* st = &stage[warp][0];

    float cacc[32];
    #pragma unroll
    for (int k = 0; k < 32; k++) cacc[k] = 0.f;

    #pragma unroll 1
    for (int g = 0; g < 4; g++) {
        const int row = (blockIdx.x << 5) + (g << 3) + warp;
        const float* p = s + ((size_t)b << 20) + ((size_t)row << 10);

        float sum = 0.f;
        #pragma unroll
        for (int k = 0; k < 8; k++) {
            const int j = (lane << 2) + (k << 7);
            float4 sv = __ldcs(reinterpret_cast<const float4*>(p + j));
            if (USE_C) {
                float4 cv = *reinterpret_cast<const float4*>(&c_s[j]);
                sv.x -= cv.x; sv.y -= cv.y; sv.z -= cv.z; sv.w -= cv.w;
            }
            float4 ev;
            ev.x = __expf(sv.x); ev.y = __expf(sv.y);
            ev.z = __expf(sv.z); ev.w = __expf(sv.w);
            *reinterpret_cast<float4*>(&st[j]) = ev;   // same-lane spill
            sum += (ev.x + ev.y) + (ev.z + ev.w);
        }
        #pragma unroll
        for (int off = 16; off; off >>= 1)
            sum += __shfl_xor_sync(0xffffffffu, sum, off);

        if (lane == 0) g_R[b * N + row] = logf(sum);  // final pass's R feeds out_pass
        const float rinv = __fdividef(1.f, sum);

        // column partials: exp(v - C - R) = e * rinv  (read back own spill)
        #pragma unroll
        for (int k = 0; k < 8; k++) {
            const int j = (lane << 2) + (k << 7);
            float4 ev = *reinterpret_cast<const float4*>(&st[j]);
            cacc[4*k+0] = fmaf(ev.x, rinv, cacc[4*k+0]);
            cacc[4*k+1] = fmaf(ev.y, rinv, cacc[4*k+1]);
            cacc[4*k+2] = fmaf(ev.z, rinv, cacc[4*k+2]);
            cacc[4*k+3] = fmaf(ev.w, rinv, cacc[4*k+3]);
        }
    }

    // single cross-warp reduce of column partials (reuse stage)
    #pragma unroll
    for (int k = 0; k < 8; k++) {
        const int j = (lane << 2) + (k << 7);
        float4 v = make_float4(cacc[4*k+0], cacc[4*k+1], cacc[4*k+2], cacc[4*k+3]);
        *reinterpret_cast<float4*>(&st[j]) = v;
    }
    __syncthreads();

    float4 a = make_float4(0.f, 0.f, 0.f, 0.f);
    #pragma unroll
    for (int w = 0; w < 8; w++) {
        float4 sv = *reinterpret_cast<const float4*>(&stage[w][tid << 2]);
        a.x += sv.x; a.y += sv.y; a.z += sv.z; a.w += sv.w;
    }
    __stcs(reinterpret_cast<float4*>(
               &g_part[((size_t)(b * RBLKS + blockIdx.x)) * N]) + tid, a);
}

// ---------------------------------------------------------------------------
// Finalize: C_new[b][j] = log( sum over RBLKS row-block partials ) + C_old.
// FIRST=true: pass ran with C==0 -> write log(sum) directly (must NOT read
// g_C: it holds stale values from the previous graph replay).
// Thread per column; partials are L2-resident. grid = 256 CTAs.
// ---------------------------------------------------------------------------
template <bool FIRST>
__global__ void __launch_bounds__(256) finalize_col() {
    const int idx = blockIdx.x * 256 + threadIdx.x;   // b*N + j
    const int b = idx >> 10, j = idx & (N - 1);
    float sum = 0.f;
    #pragma unroll
    for (int r = 0; r < RBLKS; r++)
        sum += g_part[((size_t)(b * RBLKS + r)) * N + j];
    if (FIRST) g_C[idx] = logf(sum);
    else       g_C[idx] = logf(sum) + g_C[idx];
}

// ---------------------------------------------------------------------------
// Output pass: out = exp(s - R[b][i] - C[b][j]), float4, streaming hints.
// ---------------------------------------------------------------------------
__global__ void __launch_bounds__(256) out_pass(const float4* __restrict__ s4,
                                                float4* __restrict__ o4) {
    const size_t gid  = (size_t)blockIdx.x * 256 + threadIdx.x;
    const size_t base = gid << 2;
    const int b = (int)(base >> 20);
    const int i = (int)(base >> 10) & (N - 1);
    const int j = (int)base & (N - 1);
    const float r = __ldg(&g_R[(b << 10) + i]);
    const float4 c = *reinterpret_cast<const float4*>(&g_C[(b << 10) + j]);
    float4 v = __ldcs(s4 + gid);
    float4 o;
    o.x = __expf(v.x - r - c.x);
    o.y = __expf(v.y - r - c.y);
    o.z = __expf(v.z - r - c.z);
    o.w = __expf(v.w - r - c.w);
    __stcs(o4 + gid, o);
}

// ---------------------------------------------------------------------------
extern "C" void kernel_launch(void* const* d_in, const int* in_sizes, int n_in,
                              void* d_out, int out_size) {
    const float* s = (const float*)d_in[0];
    float* out = (float*)d_out;

    const dim3 fgrid(RBLKS, BATCH);
    const int fin_blocks = BATCH * N / 256;           // 256
    const int out_blocks = (BATCH * N * N / 4) / 256;

    // iters 0+1
    fused_pass<false><<<fgrid, 256>>>(s);
    finalize_col<true><<<fin_blocks, 256>>>();
    // iters 2+3, 4+5, 6+7, 8+9
    fused_pass<true><<<fgrid, 256>>>(s);
    finalize_col<false><<<fin_blocks, 256>>>();
    fused_pass<true><<<fgrid, 256>>>(s);
    finalize_col<false><<<fin_blocks, 256>>>();
    fused_pass<true><<<fgrid, 256>>>(s);
    finalize_col<false><<<fin_blocks, 256>>>();
    fused_pass<true><<<fgrid, 256>>>(s);
    finalize_col<false><<<fin_blocks, 256>>>();

    out_pass<<<out_blocks, 256>>>((const float4*)s, (float4*)out);
}

// round 6
// speedup vs baseline: 1.0908x; 1.0908x over previous
#include <cuda_runtime.h>
#include <cuda_fp16.h>
#include <math_constants.h>

#define BATCH 64
#define N 1024
#define RBLKS 32            // row-blocks per batch (32 rows each)

// Scratch: row offsets R[b][i], col offsets C[b][j], per-CTA column partials
__device__ float g_R[BATCH * N];
__device__ float g_C[BATCH * N];
__device__ float g_part[BATCH * RBLKS * N];   // 8 MB, stays L2-resident

// ---------------------------------------------------------------------------
// Fused pass (one read of s does a row iteration AND a column iteration):
//   per row i:  sum_i = sum_j exp(s[i][j] - C[j]);  R[i] = log(sum_i)
//   column partials: part[j] += sum_i exp(s[i][j] - C[j] - R[i])
// finalize_col forms C_new[j] = log(sum_blocks part) + C_old[j].
// Warp-per-row, 4 rows per warp. e and cacc are stored as __half2 (16+16
// regs) so the kernel fits ~50 regs -> 4-5 CTAs/SM -> enough LDG in flight
// to cover DRAM latency. Row sums / R stay fp32.
// grid = (RBLKS, BATCH), block = 256 (8 warps).
// ---------------------------------------------------------------------------
template <bool USE_C>
__global__ void __launch_bounds__(256) fused_pass(const float* __restrict__ s) {
    __shared__ float c_s[N];
    __shared__ float stage[8][N];      // 32 KB, used once at the end
    const int b = blockIdx.y;
    if (USE_C) {
        #pragma unroll
        for (int t = threadIdx.x; t < N; t += 256) c_s[t] = g_C[b * N + t];
        __syncthreads();
    }

    const int warp = threadIdx.x >> 5;
    const int lane = threadIdx.x & 31;
    const int tid  = threadIdx.x;

    __half2 cacc[16];
    #pragma unroll
    for (int k = 0; k < 16; k++) cacc[k] = __float2half2_rn(0.f);

    #pragma unroll 1
    for (int g = 0; g < 4; g++) {
        const int row = (blockIdx.x << 5) + (g << 3) + warp;
        const float* p = s + ((size_t)b << 20) + ((size_t)row << 10);

        __half2 eh[16];
        float sum = 0.f;
        #pragma unroll
        for (int k = 0; k < 8; k++) {
            const int j = (lane << 2) + (k << 7);
            float4 sv = __ldcs(reinterpret_cast<const float4*>(p + j));
            if (USE_C) {
                float4 cv = *reinterpret_cast<const float4*>(&c_s[j]);
                sv.x -= cv.x; sv.y -= cv.y; sv.z -= cv.z; sv.w -= cv.w;
            }
            const float ex = __expf(sv.x), ey = __expf(sv.y);
            const float ez = __expf(sv.z), ew = __expf(sv.w);
            eh[2*k+0] = __floats2half2_rn(ex, ey);
            eh[2*k+1] = __floats2half2_rn(ez, ew);
            sum += (ex + ey) + (ez + ew);
        }
        #pragma unroll
        for (int off = 16; off; off >>= 1)
            sum += __shfl_xor_sync(0xffffffffu, sum, off);

        if (lane == 0) g_R[b * N + row] = logf(sum);  // final pass's R feeds out_pass
        const __half2 rin = __float2half2_rn(__fdividef(1.f, sum));

        // column partials: exp(v - C - R) = e * (1/sum)
        #pragma unroll
        for (int k = 0; k < 16; k++) cacc[k] = __hfma2(eh[k], rin, cacc[k]);
    }

    // single cross-warp reduce of column partials (fp32 from here on)
    #pragma unroll
    for (int k = 0; k < 8; k++) {
        const int j = (lane << 2) + (k << 7);
        const float2 lo = __half22float2(cacc[2*k+0]);
        const float2 hi = __half22float2(cacc[2*k+1]);
        *reinterpret_cast<float4*>(&stage[warp][j]) = make_float4(lo.x, lo.y, hi.x, hi.y);
    }
    __syncthreads();

    float4 a = make_float4(0.f, 0.f, 0.f, 0.f);
    #pragma unroll
    for (int w = 0; w < 8; w++) {
        float4 sv = *reinterpret_cast<const float4*>(&stage[w][tid << 2]);
        a.x += sv.x; a.y += sv.y; a.z += sv.z; a.w += sv.w;
    }
    // NORMAL store: partials must stay L2-resident for finalize_col
    reinterpret_cast<float4*>(
        &g_part[((size_t)(b * RBLKS + blockIdx.x)) * N])[tid] = a;
}

// ---------------------------------------------------------------------------
// Finalize: C_new[b][j] = log( sum over RBLKS row-block partials ) + C_old.
// FIRST=true: pass ran with C==0 -> write log(sum) directly (must NOT read
// g_C: it holds stale values from the previous graph replay).
// Partials are L2-resident (normal loads). grid = 256 CTAs.
// ---------------------------------------------------------------------------
template <bool FIRST>
__global__ void __launch_bounds__(256) finalize_col() {
    const int idx = blockIdx.x * 256 + threadIdx.x;   // b*N + j
    const int b = idx >> 10, j = idx & (N - 1);
    float sum = 0.f;
    #pragma unroll
    for (int r = 0; r < RBLKS; r++)
        sum += g_part[((size_t)(b * RBLKS + r)) * N + j];
    if (FIRST) g_C[idx] = logf(sum);
    else       g_C[idx] = logf(sum) + g_C[idx];
}

// ---------------------------------------------------------------------------
// Output pass: out = exp(s - R[b][i] - C[b][j]), float4, streaming hints.
// ---------------------------------------------------------------------------
__global__ void __launch_bounds__(256) out_pass(const float4* __restrict__ s4,
                                                float4* __restrict__ o4) {
    const size_t gid  = (size_t)blockIdx.x * 256 + threadIdx.x;
    const size_t base = gid << 2;
    const int b = (int)(base >> 20);
    const int i = (int)(base >> 10) & (N - 1);
    const int j = (int)base & (N - 1);
    const float r = __ldg(&g_R[(b << 10) + i]);
    const float4 c = *reinterpret_cast<const float4*>(&g_C[(b << 10) + j]);
    float4 v = __ldcs(s4 + gid);
    float4 o;
    o.x = __expf(v.x - r - c.x);
    o.y = __expf(v.y - r - c.y);
    o.z = __expf(v.z - r - c.z);
    o.w = __expf(v.w - r - c.w);
    __stcs(o4 + gid, o);
}

// ---------------------------------------------------------------------------
extern "C" void kernel_launch(void* const* d_in, const int* in_sizes, int n_in,
                              void* d_out, int out_size) {
    const float* s = (const float*)d_in[0];
    float* out = (float*)d_out;

    const dim3 fgrid(RBLKS, BATCH);
    const int fin_blocks = BATCH * N / 256;           // 256
    const int out_blocks = (BATCH * N * N / 4) / 256;

    // iters 0+1
    fused_pass<false><<<fgrid, 256>>>(s);
    finalize_col<true><<<fin_blocks, 256>>>();
    // iters 2+3, 4+5, 6+7, 8+9
    fused_pass<true><<<fgrid, 256>>>(s);
    finalize_col<false><<<fin_blocks, 256>>>();
    fused_pass<true><<<fgrid, 256>>>(s);
    finalize_col<false><<<fin_blocks, 256>>>();
    fused_pass<true><<<fgrid, 256>>>(s);
    finalize_col<false><<<fin_blocks, 256>>>();
    fused_pass<true><<<fgrid, 256>>>(s);
    finalize_col<false><<<fin_blocks, 256>>>();

    out_pass<<<out_blocks, 256>>>((const float4*)s, (float4*)out);
}